// round 15
// baseline (speedup 1.0000x reference)
#include <cuda_runtime.h>
#include <cuda_fp16.h>
#include <cstdint>

// ---------------- problem constants ----------------
#define BB   16
#define NN   1025
#define CC   384
#define HH   6
#define HD   64
#define HID  1536
#define MTOT (BB*NN)      // 16400
#define MTOK (BB*1024)    // 16384

// ---------------- scratch (device globals, no alloc) ----------------
__device__ __half g_hh  [MTOT*CC];
__device__ __half g_qkvh[MTOT*3*CC];
__device__ __half g_oh  [MTOT*CC];
__device__ float  g_x1  [MTOT*CC];
__device__ __half g_h2h [MTOT*CC];
__device__ __half g_yh  [(size_t)MTOK*HID];
__device__ __half g_y2h [(size_t)MTOK*HID];
__device__ float  g_part2[BB*CC];
__device__ float  g_w   [BB*CC];
__device__ __half g_wq  [3*CC*CC];
__device__ __half g_wp  [CC*CC];
__device__ __half g_w1  [HID*CC];
__device__ __half g_w3  [CC*HID];

__device__ __forceinline__ float gelu_f(float x){
    return 0.5f * x * (1.0f + erff(x * 0.70710678118654752f));
}

__device__ __forceinline__ void mma_f16(float* c, const uint32_t* a, const uint32_t* b){
    asm volatile("mma.sync.aligned.m16n8k16.row.col.f32.f16.f16.f32 "
        "{%0,%1,%2,%3}, {%4,%5,%6,%7}, {%8,%9}, {%0,%1,%2,%3};"
        : "+f"(c[0]), "+f"(c[1]), "+f"(c[2]), "+f"(c[3])
        : "r"(a[0]), "r"(a[1]), "r"(a[2]), "r"(a[3]), "r"(b[0]), "r"(b[1]));
}

__device__ __forceinline__ void ldsm4(uint32_t* r, uint32_t addr){
    asm volatile("ldmatrix.sync.aligned.m8n8.x4.shared.b16 {%0,%1,%2,%3}, [%4];"
        : "=r"(r[0]), "=r"(r[1]), "=r"(r[2]), "=r"(r[3]) : "r"(addr));
}
__device__ __forceinline__ void ldsm4t(uint32_t* r, uint32_t addr){
    asm volatile("ldmatrix.sync.aligned.m8n8.x4.trans.shared.b16 {%0,%1,%2,%3}, [%4];"
        : "=r"(r[0]), "=r"(r[1]), "=r"(r[2]), "=r"(r[3]) : "r"(addr));
}

__device__ __forceinline__ uint32_t smem_u32(const void* p){
    return (uint32_t)__cvta_generic_to_shared(p);
}
__device__ __forceinline__ void cp16(uint32_t dst, const void* src, bool pred){
    int sz = pred ? 16 : 0;
    asm volatile("cp.async.ca.shared.global [%0], [%1], 16, %2;"
                 :: "r"(dst), "l"(src), "r"(sz));
}
__device__ __forceinline__ void cp_commit(){ asm volatile("cp.async.commit_group;"); }
__device__ __forceinline__ void cp_wait0(){ asm volatile("cp.async.wait_group 0;"); }
__device__ __forceinline__ void cp_wait1(){ asm volatile("cp.async.wait_group 1;"); }

__device__ __forceinline__ uint32_t pack_h2(float x, float y){
    __half2 h = __floats2half2_rn(x, y);
    return *reinterpret_cast<uint32_t*>(&h);
}

// ---------------- fused fp32 -> fp16 weight convert + psum zero (one launch) --------
#define NW0 (3*CC*CC)
#define NW1 (CC*CC)
#define NW2 (HID*CC)
#define NW3 (CC*HID)
__global__ void f2h_all(const float* __restrict__ s0, __half* __restrict__ d0,
                        const float* __restrict__ s1, __half* __restrict__ d1,
                        const float* __restrict__ s2, __half* __restrict__ d2,
                        const float* __restrict__ s3, __half* __restrict__ d3,
                        float* __restrict__ psum)
{
    int i2 = blockIdx.x*256 + threadIdx.x;       // index in float2 units
    int stride = gridDim.x*256;
    if (i2 < BB*CC) psum[i2] = 0.f;
    const int t0 = NW0/2, t1 = t0 + NW1/2, t2 = t1 + NW2/2, t3 = t2 + NW3/2;
    for (; i2 < t3; i2 += stride){
        const float2* s; __half2* d; int off;
        if (i2 < t0){ s = (const float2*)s0; d = (__half2*)d0; off = i2; }
        else if (i2 < t1){ s = (const float2*)s1; d = (__half2*)d1; off = i2 - t0; }
        else if (i2 < t2){ s = (const float2*)s2; d = (__half2*)d2; off = i2 - t1; }
        else { s = (const float2*)s3; d = (__half2*)d3; off = i2 - t2; }
        float2 v = s[off];
        d[off] = __floats2half2_rn(v.x, v.y);
    }
}

// ---------------- LayerNorm over last dim (C=384), fp16 out ----------------
__global__ void ln_kernel(const float* __restrict__ x, const float* __restrict__ g,
                          const float* __restrict__ bta, __half* __restrict__ out)
{
    __shared__ float red[4];
    __shared__ float bc[2];
    int row = blockIdx.x;
    const float* xr = x + (size_t)row * CC;
    int t = threadIdx.x;                      // 128 threads
    float v0 = xr[t], v1 = xr[t+128], v2 = xr[t+256];
    float s = v0 + v1 + v2;
    #pragma unroll
    for (int o=16;o;o>>=1) s += __shfl_xor_sync(0xffffffffu, s, o);
    if ((t&31)==0) red[t>>5] = s;
    __syncthreads();
    if (t==0) bc[0] = (red[0]+red[1]+red[2]+red[3]) * (1.0f/CC);
    __syncthreads();
    float mu = bc[0];
    float d0=v0-mu, d1=v1-mu, d2=v2-mu;
    float q = d0*d0 + d1*d1 + d2*d2;
    #pragma unroll
    for (int o=16;o;o>>=1) q += __shfl_xor_sync(0xffffffffu, q, o);
    if ((t&31)==0) red[t>>5] = q;
    __syncthreads();
    if (t==0) bc[1] = rsqrtf((red[0]+red[1]+red[2]+red[3]) * (1.0f/CC) + 1e-5f);
    __syncthreads();
    float rs = bc[1];
    __half* orow = out + (size_t)row * CC;
    orow[t]     = __float2half(d0*rs*g[t]     + bta[t]);
    orow[t+128] = __float2half(d1*rs*g[t+128] + bta[t+128]);
    orow[t+256] = __float2half(d2*rs*g[t+256] + bta[t+256]);
}

// ---------------- fp16 mma.sync GEMM, 2-stage pipeline, 3 CTAs/SM ----------------
// EPI: 0 fp16 out | 1 fp32 resid+bias | 2 fp16 bias+BN+GELU |
//      4 fp32 bias+BN+resid remapped + colsum atomics | 5 fp16 out, q-cols x0.125
#define SPAD 36
#define BUFW (2*128*SPAD)
#define GEMM_SMEM (2*BUFW*4)

template<int EPI, bool SKIP>
__global__ void __launch_bounds__(256, 3) gemm_h(
    const __half* __restrict__ A, const __half* __restrict__ W, void* __restrict__ Cv,
    int M, int N, int K,
    const float* __restrict__ bias, const float* __restrict__ scale,
    const float* __restrict__ shift, const float* __restrict__ residual,
    float* __restrict__ psum)
{
    extern __shared__ uint32_t smg[];
    const int tid  = threadIdx.x;
    const int lane = tid & 31;
    const int warp = tid >> 5;
    const int wm = (warp & 1) * 64;
    const int wn = (warp >> 1) * 32;
    const int m0 = blockIdx.y * 128, n0 = blockIdx.x * 128;
    const int f = tid & 7;
    const int r = tid >> 3;
    const int g4 = lane >> 2;
    const int q4 = lane & 3;
    const int nk = K / 64;
    const int arow = lane & 15;
    const int acol = 4*(lane >> 4);
    const int brow = (lane & 7) + ((lane >> 4) & 1)*8;
    const int bcol = 4*((lane >> 3) & 1);

    float c[4][4][4];
    #pragma unroll
    for (int i=0;i<4;i++)
        #pragma unroll
        for (int j=0;j<4;j++)
            #pragma unroll
            for (int e=0;e<4;e++) c[i][j][e] = 0.f;

    auto stage = [&](int kb, int bf){
        uint32_t* As = smg + bf*BUFW;
        uint32_t* Bs = As + 128*SPAD;
        int k0 = kb * 64 + f * 8;
        #pragma unroll
        for (int i = 0; i < 4; i++){
            int row = r + 32*i;
            int m = m0 + row;
            bool p = (m < M);
            int gr = 0;
            if (p) gr = SKIP ? ((m >> 10)*1025 + (m & 1023) + 1) : m;
            cp16(smem_u32(As + row*SPAD + 4*f), A + (size_t)gr*K + k0, p);
        }
        #pragma unroll
        for (int i = 0; i < 4; i++){
            int row = r + 32*i;
            cp16(smem_u32(Bs + row*SPAD + 4*f), W + (size_t)(n0+row)*K + k0, true);
        }
    };

    stage(0, 0); cp_commit();

    for (int kb = 0; kb < nk; kb++){
        if (kb + 1 < nk){ stage(kb+1, (kb+1)&1); cp_commit(); cp_wait1(); }
        else cp_wait0();
        __syncthreads();
        const uint32_t* Au = smg + (kb&1)*BUFW;
        const uint32_t* Bu = Au + 128*SPAD;
        #pragma unroll
        for (int ks = 0; ks < 4; ks++){
            uint32_t a[4][4], bt[2][4];
            #pragma unroll
            for (int i=0;i<4;i++)
                ldsm4(a[i], smem_u32(Au + (wm + 16*i + arow)*SPAD + ks*8 + acol));
            ldsm4(bt[0], smem_u32(Bu + (wn +      brow)*SPAD + ks*8 + bcol));
            ldsm4(bt[1], smem_u32(Bu + (wn + 16 + brow)*SPAD + ks*8 + bcol));
            #pragma unroll
            for (int i=0;i<4;i++){
                mma_f16(c[i][0], a[i], &bt[0][0]);
                mma_f16(c[i][1], a[i], &bt[0][2]);
                mma_f16(c[i][2], a[i], &bt[1][0]);
                mma_f16(c[i][3], a[i], &bt[1][2]);
            }
        }
        __syncthreads();
    }
    // ---- epilogue ----
    if (EPI == 4){
        float* C = (float*)Cv;
        const int bidx = m0 >> 10;
        float colsum[8];
        #pragma unroll
        for (int e=0;e<8;e++) colsum[e] = 0.f;
        #pragma unroll
        for (int i=0;i<4;i++){
            #pragma unroll
            for (int hh=0; hh<2; hh++){
                int m = m0 + wm + 16*i + g4 + 8*hh;
                size_t orow = (size_t)((m >> 10)*1025 + (m & 1023) + 1);
                #pragma unroll
                for (int j=0;j<4;j++){
                    int n = n0 + wn + 8*j + 2*q4;
                    float vx = (c[i][j][hh*2+0] + bias[n])  *scale[n]   + shift[n];
                    float vy = (c[i][j][hh*2+1] + bias[n+1])*scale[n+1] + shift[n+1];
                    colsum[2*j]   += vx;
                    colsum[2*j+1] += vy;
                    float2 rv = *(const float2*)(residual + orow*N + n);
                    float2 ov; ov.x = vx + rv.x; ov.y = vy + rv.y;
                    *(float2*)(C + orow*N + n) = ov;
                }
            }
        }
        #pragma unroll
        for (int e=0;e<8;e++){
            float v = colsum[e];
            v += __shfl_xor_sync(0xffffffffu, v, 4);
            v += __shfl_xor_sync(0xffffffffu, v, 8);
            v += __shfl_xor_sync(0xffffffffu, v, 16);
            if ((lane >> 2) == 0){
                int n = n0 + wn + 8*(e>>1) + 2*(lane&3) + (e&1);
                atomicAdd(&psum[bidx*CC + n], v);
            }
        }
        return;
    }
    #pragma unroll
    for (int i=0;i<4;i++){
        int mrow0 = m0 + wm + 16*i + g4;
        #pragma unroll
        for (int hh=0; hh<2; hh++){
            int m = mrow0 + 8*hh;
            if (m >= M) continue;
            #pragma unroll
            for (int j=0;j<4;j++){
                int n = n0 + wn + 8*j + 2*q4;
                float vx = c[i][j][hh*2 + 0];
                float vy = c[i][j][hh*2 + 1];
                size_t idx = (size_t)m*N + n;
                if (EPI == 0){
                    *(uint32_t*)((__half*)Cv + idx) = pack_h2(vx, vy);
                } else if (EPI == 5){
                    float qs = (n < CC) ? 0.125f : 1.0f;
                    *(uint32_t*)((__half*)Cv + idx) = pack_h2(vx*qs, vy*qs);
                } else if (EPI == 1){
                    float* C = (float*)Cv;
                    float2 rv = *(const float2*)(residual + idx);
                    float2 ov; ov.x = vx + bias[n] + rv.x; ov.y = vy + bias[n+1] + rv.y;
                    *(float2*)(C + idx) = ov;
                } else if (EPI == 2){
                    vx = gelu_f((vx + bias[n])  *scale[n]   + shift[n]);
                    vy = gelu_f((vy + bias[n+1])*scale[n+1] + shift[n+1]);
                    *(uint32_t*)((__half*)Cv + idx) = pack_h2(vx, vy);
                }
            }
        }
    }
}

// ---------------- fp16 flash attention (Q pre-scaled), 3 CTAs/SM ----------
#define ATTN_SMEM ((128*36 + 2*128*36)*4)      // Q + 2x(K64+V64)
__global__ void __launch_bounds__(256, 3) attn_h(const __half* __restrict__ qkv,
                                                 __half* __restrict__ o)
{
    extern __shared__ uint32_t sm[];
    uint32_t* Qu  = sm;                 // [128][36]

    const int tid  = threadIdx.x;
    const int lane = tid & 31;
    const int warp = tid >> 5;
    const int g4 = lane >> 2, q4 = lane & 3;
    const int pair = blockIdx.x % 9;
    const int bh   = blockIdx.x / 9;
    const int h = bh % HH, b = bh / HH;
    const int q0 = pair * 128;
    const int qrow = warp * 16;
    const int arow = lane & 15;
    const int acol = 4*(lane >> 4);
    const int brow = (lane & 7) + ((lane >> 4) & 1)*8;
    const int bcol = 4*((lane >> 3) & 1);
    const int vtile = lane >> 3;
    const int vrow  = (lane & 7) + (vtile & 1)*8;
    const int vcol  = (vtile >> 1)*8;

    const __half* qp = qkv + (size_t)b*NN*(3*CC) + h*HD;
    const __half* kp = qp + CC;
    const __half* vp = qp + 2*CC;

    const int f  = tid & 7;
    const int rg = tid >> 3;            // 0..31

    // stage Q (128 rows)
    #pragma unroll
    for (int i=0;i<4;i++){
        int row = rg + 32*i;
        int q = q0 + row;
        bool p = (q < NN);
        cp16(smem_u32(Qu + row*36 + 4*f), qp + (size_t)(p ? q : 0)*(3*CC) + 8*f, p);
    }

    auto stage_kv = [&](int kt, int bf){
        uint32_t* Ku = sm + 128*36 + bf*128*36;
        uint32_t* Vs = Ku + 64*36;
        #pragma unroll
        for (int i=0;i<2;i++){
            int row = rg + 32*i;
            int kk = kt*64 + row;
            bool p = (kk < NN);
            size_t off = (size_t)(p ? kk : 0)*(3*CC) + 8*f;
            cp16(smem_u32(Ku + row*36 + 4*f), kp + off, p);
            cp16(smem_u32(Vs + row*36 + 4*f), vp + off, p);
        }
    };

    stage_kv(0, 0);
    cp_commit();

    float oa[8][4];
    #pragma unroll
    for (int j=0;j<8;j++){ oa[j][0]=0.f; oa[j][1]=0.f; oa[j][2]=0.f; oa[j][3]=0.f; }
    float m0r = -1e30f, m1r = -1e30f, l0r = 0.f, l1r = 0.f;

    for (int kt = 0; kt < 17; kt++){
        cp_wait0();
        __syncthreads();
        if (kt + 1 < 17){ stage_kv(kt+1, (kt+1)&1); cp_commit(); }
        const uint32_t* Ku = sm + 128*36 + (kt&1)*128*36;
        const uint32_t* Vs = Ku + 64*36;

        // ---- S = Q K^T (Q already scaled by 1/8) ----
        float sc[8][4];
        #pragma unroll
        for (int j=0;j<8;j++){ sc[j][0]=0.f; sc[j][1]=0.f; sc[j][2]=0.f; sc[j][3]=0.f; }
        #pragma unroll
        for (int ks=0; ks<4; ks++){
            uint32_t a[4];
            ldsm4(a, smem_u32(Qu + (qrow + arow)*36 + ks*8 + acol));
            #pragma unroll
            for (int j2=0; j2<4; j2++){
                uint32_t bt[4];
                ldsm4(bt, smem_u32(Ku + (16*j2 + brow)*36 + ks*8 + bcol));
                mma_f16(sc[2*j2],   a, &bt[0]);
                mma_f16(sc[2*j2+1], a, &bt[2]);
            }
        }
        if (kt == 16){
            #pragma unroll
            for (int j=0;j<8;j++){
                int c0 = kt*64 + 8*j + 2*q4;
                if (c0   >= NN){ sc[j][0] = -1e30f; sc[j][2] = -1e30f; }
                if (c0+1 >= NN){ sc[j][1] = -1e30f; sc[j][3] = -1e30f; }
            }
        }
        // ---- online softmax ----
        float mx0 = -1e30f, mx1 = -1e30f;
        #pragma unroll
        for (int j=0;j<8;j++){
            mx0 = fmaxf(mx0, fmaxf(sc[j][0], sc[j][1]));
            mx1 = fmaxf(mx1, fmaxf(sc[j][2], sc[j][3]));
        }
        mx0 = fmaxf(mx0, __shfl_xor_sync(0xffffffffu, mx0, 1));
        mx0 = fmaxf(mx0, __shfl_xor_sync(0xffffffffu, mx0, 2));
        mx1 = fmaxf(mx1, __shfl_xor_sync(0xffffffffu, mx1, 1));
        mx1 = fmaxf(mx1, __shfl_xor_sync(0xffffffffu, mx1, 2));
        float mn0 = fmaxf(m0r, mx0), mn1 = fmaxf(m1r, mx1);
        float al0 = __expf(m0r - mn0), al1 = __expf(m1r - mn1);
        float s0 = 0.f, s1 = 0.f;
        #pragma unroll
        for (int j=0;j<8;j++){
            float p00 = __expf(sc[j][0]-mn0), p01 = __expf(sc[j][1]-mn0);
            float p10 = __expf(sc[j][2]-mn1), p11 = __expf(sc[j][3]-mn1);
            sc[j][0]=p00; sc[j][1]=p01; sc[j][2]=p10; sc[j][3]=p11;
            s0 += p00 + p01; s1 += p10 + p11;
        }
        s0 += __shfl_xor_sync(0xffffffffu, s0, 1);
        s0 += __shfl_xor_sync(0xffffffffu, s0, 2);
        s1 += __shfl_xor_sync(0xffffffffu, s1, 1);
        s1 += __shfl_xor_sync(0xffffffffu, s1, 2);
        l0r = l0r*al0 + s0; l1r = l1r*al1 + s1;
        m0r = mn0; m1r = mn1;
        #pragma unroll
        for (int j=0;j<8;j++){
            oa[j][0]*=al0; oa[j][1]*=al0; oa[j][2]*=al1; oa[j][3]*=al1;
        }
        // ---- O += P V : P direct from registers, V via ldmatrix.trans ----
        #pragma unroll
        for (int ks=0; ks<4; ks++){
            uint32_t a[4];
            a[0] = pack_h2(sc[2*ks][0],   sc[2*ks][1]);
            a[1] = pack_h2(sc[2*ks][2],   sc[2*ks][3]);
            a[2] = pack_h2(sc[2*ks+1][0], sc[2*ks+1][1]);
            a[3] = pack_h2(sc[2*ks+1][2], sc[2*ks+1][3]);
            #pragma unroll
            for (int j=0;j<4;j++){
                uint32_t bt[4];
                ldsm4t(bt, smem_u32(Vs + (16*ks + vrow)*36 + (16*j + vcol)/2));
                mma_f16(oa[2*j],   a, &bt[0]);
                mma_f16(oa[2*j+1], a, &bt[2]);
            }
        }
        // next iteration's top __syncthreads guards buffer reuse
    }
    float inv0 = 1.0f / l0r, inv1 = 1.0f / l1r;
    int qg0 = q0 + qrow + g4, qg1 = qg0 + 8;
    #pragma unroll
    for (int j=0;j<8;j++){
        int d = h*HD + 8*j + 2*q4;
        if (qg0 < NN)
            *(uint32_t*)(o + (size_t)(b*NN + qg0)*CC + d) = pack_h2(oa[j][0]*inv0, oa[j][1]*inv0);
        if (qg1 < NN)
            *(uint32_t*)(o + (size_t)(b*NN + qg1)*CC + d) = pack_h2(oa[j][2]*inv1, oa[j][3]*inv1);
    }
}

// ---------------- depthwise 3x3, 4 pixels per block (3x reuse) ----------------
__global__ void __launch_bounds__(256) dwconv_q4(
    const __half2* __restrict__ y, const float* __restrict__ w2,
    const float* __restrict__ b2, const float* __restrict__ s2,
    const float* __restrict__ h2b, __half2* __restrict__ out)
{
    int grp = blockIdx.x;            // 0..4095
    int b = grp >> 8;                // 256 4-pixel groups per image
    int p4 = (grp & 255) * 4;
    int sy = p4 >> 5, sx0 = p4 & 31;
    const __half2* yb = y + (size_t)(b << 10) * 768;
    for (int c2 = threadIdx.x; c2 < 768; c2 += 256){
        int c = 2*c2;
        float w[9][2];
        #pragma unroll
        for (int t=0;t<9;t++){ w[t][0]=w2[c*9+t]; w[t][1]=w2[(c+1)*9+t]; }
        float bb0=b2[c], bb1=b2[c+1], ss0=s2[c], ss1=s2[c+1], hh0=h2b[c], hh1=h2b[c+1];
        float ax[4]={0.f,0.f,0.f,0.f}, ay[4]={0.f,0.f,0.f,0.f};
        float2 cen[4];
        #pragma unroll
        for (int dy=0; dy<3; dy++){
            int iy = sy + dy - 1;
            if ((unsigned)iy >= 32u) continue;
            #pragma unroll
            for (int dxx=0; dxx<6; dxx++){
                int ix = sx0 + dxx - 1;
                if ((unsigned)ix >= 32u) continue;
                float2 fv = __half22float2(yb[(size_t)((iy<<5)+ix)*768 + c2]);
                if (dy==1 && dxx>=1 && dxx<=4) cen[dxx-1] = fv;
                #pragma unroll
                for (int i=0;i<4;i++){
                    int dr = dxx - i;          // kernel column index
                    if (dr >= 0 && dr < 3){
                        ax[i] += fv.x * w[dy*3+dr][0];
                        ay[i] += fv.y * w[dy*3+dr][1];
                    }
                }
            }
        }
        #pragma unroll
        for (int i=0;i<4;i++){
            float vx = (ax[i] + bb0)*ss0 + hh0;
            float vy = (ay[i] + bb1)*ss1 + hh1;
            out[(size_t)((b<<10) + p4 + i)*768 + c2] =
                __floats2half2_rn(cen[i].x + gelu_f(vx), cen[i].y + gelu_f(vy));
        }
    }
}

// ---------------- SE gate ----------------
__global__ void se_kernel(const float* __restrict__ part, const float* __restrict__ cw,
                          const float* __restrict__ cb, const float* __restrict__ ew,
                          const float* __restrict__ eb, float* __restrict__ wout)
{
    __shared__ float m[CC];
    __shared__ float cv[96];
    int b = blockIdx.x, t = threadIdx.x;    // 384 threads
    m[t] = part[b*CC + t] * (1.0f/1024.0f);
    __syncthreads();
    if (t < 96){
        float a = cb[t];
        for (int k=0;k<CC;k++) a += m[k]*cw[t*CC + k];
        cv[t] = gelu_f(a);
    }
    __syncthreads();
    float a = eb[t];
    for (int k=0;k<96;k++) a += cv[k]*ew[t*96 + k];
    wout[b*CC + t] = a;
}

// ---------------- cls rows: out[b,0,:] = x1 + h2*w ----------------
__global__ void final_cls_kernel(const float* __restrict__ x1, const __half* __restrict__ h2,
                                 const float* __restrict__ w, float* __restrict__ out)
{
    int b = blockIdx.x, t = threadIdx.x;    // 384 threads
    size_t i = (size_t)b*NN*CC + t;
    out[i] = x1[i] + __half2float(h2[i]) * w[b*CC + t];
}

// ---------------- launcher ----------------
extern "C" void kernel_launch(void* const* d_in, const int* in_sizes, int n_in,
                              void* d_out, int out_size)
{
    const float* x       = (const float*)d_in[0];
    const float* ln1_g   = (const float*)d_in[1];
    const float* ln1_b   = (const float*)d_in[2];
    const float* qkv_w   = (const float*)d_in[3];
    const float* proj_w  = (const float*)d_in[4];
    const float* proj_b  = (const float*)d_in[5];
    const float* ln2_g   = (const float*)d_in[6];
    const float* ln2_b   = (const float*)d_in[7];
    const float* conv1_w = (const float*)d_in[8];
    const float* conv1_b = (const float*)d_in[9];
    const float* conv2_w = (const float*)d_in[10];
    const float* conv2_b = (const float*)d_in[11];
    const float* conv3_w = (const float*)d_in[12];
    const float* conv3_b = (const float*)d_in[13];
    const float* bn1_s   = (const float*)d_in[14];
    const float* bn1_b   = (const float*)d_in[15];
    const float* bn2_s   = (const float*)d_in[16];
    const float* bn2_b   = (const float*)d_in[17];
    const float* bn3_s   = (const float*)d_in[18];
    const float* bn3_b   = (const float*)d_in[19];
    const float* comp_w  = (const float*)d_in[20];
    const float* comp_b  = (const float*)d_in[21];
    const float* exc_w   = (const float*)d_in[22];
    const float* exc_b   = (const float*)d_in[23];
    float* out = (float*)d_out;

    static bool init = false;
    static __half *p_hh, *p_qkvh, *p_oh, *p_h2h, *p_yh, *p_y2h, *p_wq, *p_wp, *p_w1, *p_w3;
    static float *p_x1, *p_part2, *p_w;
    if (!init){
        cudaGetSymbolAddress((void**)&p_hh,    g_hh);
        cudaGetSymbolAddress((void**)&p_qkvh,  g_qkvh);
        cudaGetSymbolAddress((void**)&p_oh,    g_oh);
        cudaGetSymbolAddress((void**)&p_x1,    g_x1);
        cudaGetSymbolAddress((void**)&p_h2h,   g_h2h);
        cudaGetSymbolAddress((void**)&p_yh,    g_yh);
        cudaGetSymbolAddress((void**)&p_y2h,   g_y2h);
        cudaGetSymbolAddress((void**)&p_part2, g_part2);
        cudaGetSymbolAddress((void**)&p_w,     g_w);
        cudaGetSymbolAddress((void**)&p_wq,    g_wq);
        cudaGetSymbolAddress((void**)&p_wp,    g_wp);
        cudaGetSymbolAddress((void**)&p_w1,    g_w1);
        cudaGetSymbolAddress((void**)&p_w3,    g_w3);
        cudaFuncSetAttribute(gemm_h<5,false>, cudaFuncAttributeMaxDynamicSharedMemorySize, GEMM_SMEM);
        cudaFuncSetAttribute(gemm_h<1,false>, cudaFuncAttributeMaxDynamicSharedMemorySize, GEMM_SMEM);
        cudaFuncSetAttribute(gemm_h<2,true>,  cudaFuncAttributeMaxDynamicSharedMemorySize, GEMM_SMEM);
        cudaFuncSetAttribute(gemm_h<4,false>, cudaFuncAttributeMaxDynamicSharedMemorySize, GEMM_SMEM);
        cudaFuncSetAttribute(attn_h, cudaFuncAttributeMaxDynamicSharedMemorySize, ATTN_SMEM);
        init = true;
    }

    // 0. weight conversions + psum zero (single launch)
    f2h_all<<<512, 256>>>(qkv_w, p_wq, proj_w, p_wp, conv1_w, p_w1, conv3_w, p_w3, p_part2);
    // 1. LN1 -> fp16 h
    ln_kernel<<<MTOT, 128>>>(x, ln1_g, ln1_b, p_hh);
    // 2. QKV = h @ qkv_w^T -> fp16, q columns pre-scaled by 0.125
    gemm_h<5,false><<<dim3(9,129), 256, GEMM_SMEM>>>(p_hh, p_wq, p_qkvh, MTOT, 3*CC, CC,
                                                     nullptr, nullptr, nullptr, nullptr, nullptr);
    // 3. attention -> fp16 o
    attn_h<<<BB*HH*9, 256, ATTN_SMEM>>>(p_qkvh, p_oh);
    // 4. x1 = x + o @ proj_w^T + proj_b (fp32)
    gemm_h<1,false><<<dim3(3,129), 256, GEMM_SMEM>>>(p_oh, p_wp, p_x1, MTOT, CC, CC,
                                                     proj_b, nullptr, nullptr, x, nullptr);
    // 5. LN2 -> fp16 h2
    ln_kernel<<<MTOT, 128>>>(p_x1, ln2_g, ln2_b, p_h2h);
    // 6. conv1 + BN1 + GELU -> fp16 y (tokens only)
    gemm_h<2,true><<<dim3(12,128), 256, GEMM_SMEM>>>(p_h2h, p_w1, p_yh, MTOK, HID, CC,
                                                     conv1_b, bn1_s, bn1_b, nullptr, nullptr);
    // 7. depthwise 3x3 + BN2 -> fp16 y2 (4 pixels/block)
    dwconv_q4<<<4096, 256>>>((const __half2*)p_yh, conv2_w, conv2_b, bn2_s, bn2_b,
                             (__half2*)p_y2h);
    // 8. conv3 + BN3 fused tail (writes token rows of out + column sums)
    gemm_h<4,false><<<dim3(3,128), 256, GEMM_SMEM>>>(p_y2h, p_w3, out, MTOK, CC, HID,
                                                     conv3_b, bn3_s, bn3_b, p_x1, p_part2);
    // 9. SE gate
    se_kernel<<<BB, CC>>>(p_part2, comp_w, comp_b, exc_w, exc_b, p_w);
    // 10. cls rows
    final_cls_kernel<<<BB, CC>>>(p_x1, p_h2h, p_w, out);
}

// round 16
// speedup vs baseline: 1.2360x; 1.2360x over previous
#include <cuda_runtime.h>
#include <cuda_fp16.h>
#include <cstdint>

// ---------------- problem constants ----------------
#define BB   16
#define NN   1025
#define CC   384
#define HH   6
#define HD   64
#define HID  1536
#define MTOT (BB*NN)      // 16400
#define MTOK (BB*1024)    // 16384

// ---------------- scratch (device globals, no alloc) ----------------
__device__ __half g_hh  [MTOT*CC];
__device__ __half g_qkvh[MTOT*3*CC];
__device__ __half g_oh  [MTOT*CC];
__device__ float  g_x1  [MTOT*CC];
__device__ __half g_h2h [MTOT*CC];
__device__ __half g_yh  [(size_t)MTOK*HID];
__device__ __half g_y2h [(size_t)MTOK*HID];
__device__ float  g_part2[BB*CC];
__device__ float  g_w   [BB*CC];
__device__ __half g_wq  [3*CC*CC];
__device__ __half g_wp  [CC*CC];
__device__ __half g_w1  [HID*CC];
__device__ __half g_w3  [CC*HID];

__device__ __forceinline__ float gelu_f(float x){
    return 0.5f * x * (1.0f + erff(x * 0.70710678118654752f));
}

__device__ __forceinline__ void mma_f16(float* c, const uint32_t* a, const uint32_t* b){
    asm volatile("mma.sync.aligned.m16n8k16.row.col.f32.f16.f16.f32 "
        "{%0,%1,%2,%3}, {%4,%5,%6,%7}, {%8,%9}, {%0,%1,%2,%3};"
        : "+f"(c[0]), "+f"(c[1]), "+f"(c[2]), "+f"(c[3])
        : "r"(a[0]), "r"(a[1]), "r"(a[2]), "r"(a[3]), "r"(b[0]), "r"(b[1]));
}

__device__ __forceinline__ void ldsm4(uint32_t* r, uint32_t addr){
    asm volatile("ldmatrix.sync.aligned.m8n8.x4.shared.b16 {%0,%1,%2,%3}, [%4];"
        : "=r"(r[0]), "=r"(r[1]), "=r"(r[2]), "=r"(r[3]) : "r"(addr));
}
__device__ __forceinline__ void ldsm4t(uint32_t* r, uint32_t addr){
    asm volatile("ldmatrix.sync.aligned.m8n8.x4.trans.shared.b16 {%0,%1,%2,%3}, [%4];"
        : "=r"(r[0]), "=r"(r[1]), "=r"(r[2]), "=r"(r[3]) : "r"(addr));
}

__device__ __forceinline__ uint32_t smem_u32(const void* p){
    return (uint32_t)__cvta_generic_to_shared(p);
}
__device__ __forceinline__ void cp16(uint32_t dst, const void* src, bool pred){
    int sz = pred ? 16 : 0;
    asm volatile("cp.async.ca.shared.global [%0], [%1], 16, %2;"
                 :: "r"(dst), "l"(src), "r"(sz));
}
__device__ __forceinline__ void cp_commit(){ asm volatile("cp.async.commit_group;"); }
__device__ __forceinline__ void cp_wait0(){ asm volatile("cp.async.wait_group 0;"); }
__device__ __forceinline__ void cp_wait1(){ asm volatile("cp.async.wait_group 1;"); }

__device__ __forceinline__ uint32_t pack_h2(float x, float y){
    __half2 h = __floats2half2_rn(x, y);
    return *reinterpret_cast<uint32_t*>(&h);
}

// ---------------- fused fp32 -> fp16 weight convert + psum zero (one launch) --------
#define NW0 (3*CC*CC)
#define NW1 (CC*CC)
#define NW2 (HID*CC)
#define NW3 (CC*HID)
__global__ void f2h_all(const float* __restrict__ s0, __half* __restrict__ d0,
                        const float* __restrict__ s1, __half* __restrict__ d1,
                        const float* __restrict__ s2, __half* __restrict__ d2,
                        const float* __restrict__ s3, __half* __restrict__ d3,
                        float* __restrict__ psum)
{
    int i2 = blockIdx.x*256 + threadIdx.x;       // index in float2 units
    int stride = gridDim.x*256;
    if (i2 < BB*CC) psum[i2] = 0.f;
    const int t0 = NW0/2, t1 = t0 + NW1/2, t2 = t1 + NW2/2, t3 = t2 + NW3/2;
    for (; i2 < t3; i2 += stride){
        const float2* s; __half2* d; int off;
        if (i2 < t0){ s = (const float2*)s0; d = (__half2*)d0; off = i2; }
        else if (i2 < t1){ s = (const float2*)s1; d = (__half2*)d1; off = i2 - t0; }
        else if (i2 < t2){ s = (const float2*)s2; d = (__half2*)d2; off = i2 - t1; }
        else { s = (const float2*)s3; d = (__half2*)d3; off = i2 - t2; }
        float2 v = s[off];
        d[off] = __floats2half2_rn(v.x, v.y);
    }
}

// ---------------- LayerNorm over last dim (C=384), fp16 out ----------------
__global__ void ln_kernel(const float* __restrict__ x, const float* __restrict__ g,
                          const float* __restrict__ bta, __half* __restrict__ out)
{
    __shared__ float red[4];
    __shared__ float bc[2];
    int row = blockIdx.x;
    const float* xr = x + (size_t)row * CC;
    int t = threadIdx.x;                      // 128 threads
    float v0 = xr[t], v1 = xr[t+128], v2 = xr[t+256];
    float s = v0 + v1 + v2;
    #pragma unroll
    for (int o=16;o;o>>=1) s += __shfl_xor_sync(0xffffffffu, s, o);
    if ((t&31)==0) red[t>>5] = s;
    __syncthreads();
    if (t==0) bc[0] = (red[0]+red[1]+red[2]+red[3]) * (1.0f/CC);
    __syncthreads();
    float mu = bc[0];
    float d0=v0-mu, d1=v1-mu, d2=v2-mu;
    float q = d0*d0 + d1*d1 + d2*d2;
    #pragma unroll
    for (int o=16;o;o>>=1) q += __shfl_xor_sync(0xffffffffu, q, o);
    if ((t&31)==0) red[t>>5] = q;
    __syncthreads();
    if (t==0) bc[1] = rsqrtf((red[0]+red[1]+red[2]+red[3]) * (1.0f/CC) + 1e-5f);
    __syncthreads();
    float rs = bc[1];
    __half* orow = out + (size_t)row * CC;
    orow[t]     = __float2half(d0*rs*g[t]     + bta[t]);
    orow[t+128] = __float2half(d1*rs*g[t+128] + bta[t+128]);
    orow[t+256] = __float2half(d2*rs*g[t+256] + bta[t+256]);
}

// ---------------- fp16 mma.sync GEMM, 3-stage pipeline, templated M-tile ----------
// MT = 128 (warp tile 64x32) or 64 (warp tile 32x32). CTA N-tile always 128.
// EPI: 0 fp16 out | 1 fp32 resid+bias | 2 fp16 bias+BN+GELU |
//      4 fp32 bias+BN+resid remapped + colsum atomics | 5 fp16 out, q-cols x0.125
#define SPAD 36
#define GEMM_SMEM_MT(MT) (3*((MT)+128)*SPAD*4)

template<int EPI, bool SKIP, int MT>
__global__ void __launch_bounds__(256, 2) gemm_h(
    const __half* __restrict__ A, const __half* __restrict__ W, void* __restrict__ Cv,
    int M, int N, int K,
    const float* __restrict__ bias, const float* __restrict__ scale,
    const float* __restrict__ shift, const float* __restrict__ residual,
    float* __restrict__ psum)
{
    extern __shared__ uint32_t smg[];
    constexpr int MI   = MT/32;              // m-tiles per warp
    constexpr int BUFW = (MT+128)*SPAD;
    const int tid  = threadIdx.x;
    const int lane = tid & 31;
    const int warp = tid >> 5;
    const int wm = (warp & 1) * (MT/2);
    const int wn = (warp >> 1) * 32;
    const int m0 = blockIdx.y * MT, n0 = blockIdx.x * 128;
    const int f = tid & 7;
    const int r = tid >> 3;
    const int g4 = lane >> 2;
    const int q4 = lane & 3;
    const int nk = K / 64;
    const int arow = lane & 15;
    const int acol = 4*(lane >> 4);
    const int brow = (lane & 7) + ((lane >> 4) & 1)*8;
    const int bcol = 4*((lane >> 3) & 1);

    float c[MI][4][4];
    #pragma unroll
    for (int i=0;i<MI;i++)
        #pragma unroll
        for (int j=0;j<4;j++)
            #pragma unroll
            for (int e=0;e<4;e++) c[i][j][e] = 0.f;

    auto stage = [&](int kb, int bf){
        uint32_t* As = smg + bf*BUFW;
        uint32_t* Bs = As + MT*SPAD;
        int k0 = kb * 64 + f * 8;
        #pragma unroll
        for (int i = 0; i < MT/32; i++){
            int row = r + 32*i;
            int m = m0 + row;
            bool p = (m < M);
            int gr = 0;
            if (p) gr = SKIP ? ((m >> 10)*1025 + (m & 1023) + 1) : m;
            cp16(smem_u32(As + row*SPAD + 4*f), A + (size_t)gr*K + k0, p);
        }
        #pragma unroll
        for (int i = 0; i < 4; i++){
            int row = r + 32*i;
            cp16(smem_u32(Bs + row*SPAD + 4*f), W + (size_t)(n0+row)*K + k0, true);
        }
    };

    stage(0, 0); cp_commit();
    if (nk > 1){ stage(1, 1); cp_commit(); }

    for (int kb = 0; kb < nk; kb++){
        if (kb + 1 < nk) cp_wait1(); else cp_wait0();
        __syncthreads();
        if (kb + 2 < nk){ stage(kb+2, (kb+2)%3); cp_commit(); }
        const uint32_t* Au = smg + (kb%3)*BUFW;
        const uint32_t* Bu = Au + MT*SPAD;
        #pragma unroll
        for (int ks = 0; ks < 4; ks++){
            uint32_t a[MI][4], bt[2][4];
            #pragma unroll
            for (int i=0;i<MI;i++)
                ldsm4(a[i], smem_u32(Au + (wm + 16*i + arow)*SPAD + ks*8 + acol));
            ldsm4(bt[0], smem_u32(Bu + (wn +      brow)*SPAD + ks*8 + bcol));
            ldsm4(bt[1], smem_u32(Bu + (wn + 16 + brow)*SPAD + ks*8 + bcol));
            #pragma unroll
            for (int i=0;i<MI;i++){
                mma_f16(c[i][0], a[i], &bt[0][0]);
                mma_f16(c[i][1], a[i], &bt[0][2]);
                mma_f16(c[i][2], a[i], &bt[1][0]);
                mma_f16(c[i][3], a[i], &bt[1][2]);
            }
        }
        __syncthreads();
    }
    // ---- epilogue ----
    if (EPI == 4){
        float* C = (float*)Cv;
        const int bidx = m0 >> 10;
        float colsum[8];
        #pragma unroll
        for (int e=0;e<8;e++) colsum[e] = 0.f;
        #pragma unroll
        for (int i=0;i<MI;i++){
            #pragma unroll
            for (int hh=0; hh<2; hh++){
                int m = m0 + wm + 16*i + g4 + 8*hh;
                size_t orow = (size_t)((m >> 10)*1025 + (m & 1023) + 1);
                #pragma unroll
                for (int j=0;j<4;j++){
                    int n = n0 + wn + 8*j + 2*q4;
                    float vx = (c[i][j][hh*2+0] + bias[n])  *scale[n]   + shift[n];
                    float vy = (c[i][j][hh*2+1] + bias[n+1])*scale[n+1] + shift[n+1];
                    colsum[2*j]   += vx;
                    colsum[2*j+1] += vy;
                    float2 rv = *(const float2*)(residual + orow*N + n);
                    float2 ov; ov.x = vx + rv.x; ov.y = vy + rv.y;
                    *(float2*)(C + orow*N + n) = ov;
                }
            }
        }
        #pragma unroll
        for (int e=0;e<8;e++){
            float v = colsum[e];
            v += __shfl_xor_sync(0xffffffffu, v, 4);
            v += __shfl_xor_sync(0xffffffffu, v, 8);
            v += __shfl_xor_sync(0xffffffffu, v, 16);
            if ((lane >> 2) == 0){
                int n = n0 + wn + 8*(e>>1) + 2*(lane&3) + (e&1);
                atomicAdd(&psum[bidx*CC + n], v);
            }
        }
        return;
    }
    #pragma unroll
    for (int i=0;i<MI;i++){
        int mrow0 = m0 + wm + 16*i + g4;
        #pragma unroll
        for (int hh=0; hh<2; hh++){
            int m = mrow0 + 8*hh;
            if (m >= M) continue;
            #pragma unroll
            for (int j=0;j<4;j++){
                int n = n0 + wn + 8*j + 2*q4;
                float vx = c[i][j][hh*2 + 0];
                float vy = c[i][j][hh*2 + 1];
                size_t idx = (size_t)m*N + n;
                if (EPI == 0){
                    *(uint32_t*)((__half*)Cv + idx) = pack_h2(vx, vy);
                } else if (EPI == 5){
                    float qs = (n < CC) ? 0.125f : 1.0f;
                    *(uint32_t*)((__half*)Cv + idx) = pack_h2(vx*qs, vy*qs);
                } else if (EPI == 1){
                    float* C = (float*)Cv;
                    float2 rv = *(const float2*)(residual + idx);
                    float2 ov; ov.x = vx + bias[n] + rv.x; ov.y = vy + bias[n+1] + rv.y;
                    *(float2*)(C + idx) = ov;
                } else if (EPI == 2){
                    vx = gelu_f((vx + bias[n])  *scale[n]   + shift[n]);
                    vy = gelu_f((vy + bias[n+1])*scale[n+1] + shift[n+1]);
                    *(uint32_t*)((__half*)Cv + idx) = pack_h2(vx, vy);
                }
            }
        }
    }
}

// ---------------- fp16 flash attention (Q pre-scaled; R13 version) ----------
#define ATTN_SMEM ((128*36 + 2*128*36)*4)      // Q + 2x(K64+V64)
__global__ void __launch_bounds__(256) attn_h(const __half* __restrict__ qkv,
                                              __half* __restrict__ o)
{
    extern __shared__ uint32_t sm[];
    uint32_t* Qu  = sm;                 // [128][36]

    const int tid  = threadIdx.x;
    const int lane = tid & 31;
    const int warp = tid >> 5;
    const int g4 = lane >> 2, q4 = lane & 3;
    const int pair = blockIdx.x % 9;
    const int bh   = blockIdx.x / 9;
    const int h = bh % HH, b = bh / HH;
    const int q0 = pair * 128;
    const int qrow = warp * 16;
    const int arow = lane & 15;
    const int acol = 4*(lane >> 4);
    const int brow = (lane & 7) + ((lane >> 4) & 1)*8;
    const int bcol = 4*((lane >> 3) & 1);
    const int vtile = lane >> 3;
    const int vrow  = (lane & 7) + (vtile & 1)*8;
    const int vcol  = (vtile >> 1)*8;

    const __half* qp = qkv + (size_t)b*NN*(3*CC) + h*HD;
    const __half* kp = qp + CC;
    const __half* vp = qp + 2*CC;

    const int f  = tid & 7;
    const int rg = tid >> 3;            // 0..31

    // stage Q (128 rows)
    #pragma unroll
    for (int i=0;i<4;i++){
        int row = rg + 32*i;
        int q = q0 + row;
        bool p = (q < NN);
        cp16(smem_u32(Qu + row*36 + 4*f), qp + (size_t)(p ? q : 0)*(3*CC) + 8*f, p);
    }

    auto stage_kv = [&](int kt, int bf){
        uint32_t* Ku = sm + 128*36 + bf*128*36;
        uint32_t* Vs = Ku + 64*36;
        #pragma unroll
        for (int i=0;i<2;i++){
            int row = rg + 32*i;
            int kk = kt*64 + row;
            bool p = (kk < NN);
            size_t off = (size_t)(p ? kk : 0)*(3*CC) + 8*f;
            cp16(smem_u32(Ku + row*36 + 4*f), kp + off, p);
            cp16(smem_u32(Vs + row*36 + 4*f), vp + off, p);
        }
    };

    stage_kv(0, 0);
    cp_commit();

    float oa[8][4];
    #pragma unroll
    for (int j=0;j<8;j++){ oa[j][0]=0.f; oa[j][1]=0.f; oa[j][2]=0.f; oa[j][3]=0.f; }
    float m0r = -1e30f, m1r = -1e30f, l0r = 0.f, l1r = 0.f;

    for (int kt = 0; kt < 17; kt++){
        cp_wait0();
        __syncthreads();
        if (kt + 1 < 17){ stage_kv(kt+1, (kt+1)&1); cp_commit(); }
        const uint32_t* Ku = sm + 128*36 + (kt&1)*128*36;
        const uint32_t* Vs = Ku + 64*36;

        // ---- S = Q K^T (Q already scaled by 1/8) ----
        float sc[8][4];
        #pragma unroll
        for (int j=0;j<8;j++){ sc[j][0]=0.f; sc[j][1]=0.f; sc[j][2]=0.f; sc[j][3]=0.f; }
        #pragma unroll
        for (int ks=0; ks<4; ks++){
            uint32_t a[4];
            ldsm4(a, smem_u32(Qu + (qrow + arow)*36 + ks*8 + acol));
            #pragma unroll
            for (int j2=0; j2<4; j2++){
                uint32_t bt[4];
                ldsm4(bt, smem_u32(Ku + (16*j2 + brow)*36 + ks*8 + bcol));
                mma_f16(sc[2*j2],   a, &bt[0]);
                mma_f16(sc[2*j2+1], a, &bt[2]);
            }
        }
        if (kt == 16){
            #pragma unroll
            for (int j=0;j<8;j++){
                int c0 = kt*64 + 8*j + 2*q4;
                if (c0   >= NN){ sc[j][0] = -1e30f; sc[j][2] = -1e30f; }
                if (c0+1 >= NN){ sc[j][1] = -1e30f; sc[j][3] = -1e30f; }
            }
        }
        // ---- online softmax ----
        float mx0 = -1e30f, mx1 = -1e30f;
        #pragma unroll
        for (int j=0;j<8;j++){
            mx0 = fmaxf(mx0, fmaxf(sc[j][0], sc[j][1]));
            mx1 = fmaxf(mx1, fmaxf(sc[j][2], sc[j][3]));
        }
        mx0 = fmaxf(mx0, __shfl_xor_sync(0xffffffffu, mx0, 1));
        mx0 = fmaxf(mx0, __shfl_xor_sync(0xffffffffu, mx0, 2));
        mx1 = fmaxf(mx1, __shfl_xor_sync(0xffffffffu, mx1, 1));
        mx1 = fmaxf(mx1, __shfl_xor_sync(0xffffffffu, mx1, 2));
        float mn0 = fmaxf(m0r, mx0), mn1 = fmaxf(m1r, mx1);
        float al0 = __expf(m0r - mn0), al1 = __expf(m1r - mn1);
        float s0 = 0.f, s1 = 0.f;
        #pragma unroll
        for (int j=0;j<8;j++){
            float p00 = __expf(sc[j][0]-mn0), p01 = __expf(sc[j][1]-mn0);
            float p10 = __expf(sc[j][2]-mn1), p11 = __expf(sc[j][3]-mn1);
            sc[j][0]=p00; sc[j][1]=p01; sc[j][2]=p10; sc[j][3]=p11;
            s0 += p00 + p01; s1 += p10 + p11;
        }
        s0 += __shfl_xor_sync(0xffffffffu, s0, 1);
        s0 += __shfl_xor_sync(0xffffffffu, s0, 2);
        s1 += __shfl_xor_sync(0xffffffffu, s1, 1);
        s1 += __shfl_xor_sync(0xffffffffu, s1, 2);
        l0r = l0r*al0 + s0; l1r = l1r*al1 + s1;
        m0r = mn0; m1r = mn1;
        #pragma unroll
        for (int j=0;j<8;j++){
            oa[j][0]*=al0; oa[j][1]*=al0; oa[j][2]*=al1; oa[j][3]*=al1;
        }
        // ---- O += P V : P direct from registers, V via ldmatrix.trans ----
        #pragma unroll
        for (int ks=0; ks<4; ks++){
            uint32_t a[4];
            a[0] = pack_h2(sc[2*ks][0],   sc[2*ks][1]);
            a[1] = pack_h2(sc[2*ks][2],   sc[2*ks][3]);
            a[2] = pack_h2(sc[2*ks+1][0], sc[2*ks+1][1]);
            a[3] = pack_h2(sc[2*ks+1][2], sc[2*ks+1][3]);
            #pragma unroll
            for (int j=0;j<4;j++){
                uint32_t bt[4];
                ldsm4t(bt, smem_u32(Vs + (16*ks + vrow)*36 + (16*j + vcol)/2));
                mma_f16(oa[2*j],   a, &bt[0]);
                mma_f16(oa[2*j+1], a, &bt[2]);
            }
        }
        // next iteration's top __syncthreads guards buffer reuse
    }
    float inv0 = 1.0f / l0r, inv1 = 1.0f / l1r;
    int qg0 = q0 + qrow + g4, qg1 = qg0 + 8;
    #pragma unroll
    for (int j=0;j<8;j++){
        int d = h*HD + 8*j + 2*q4;
        if (qg0 < NN)
            *(uint32_t*)(o + (size_t)(b*NN + qg0)*CC + d) = pack_h2(oa[j][0]*inv0, oa[j][1]*inv0);
        if (qg1 < NN)
            *(uint32_t*)(o + (size_t)(b*NN + qg1)*CC + d) = pack_h2(oa[j][2]*inv1, oa[j][3]*inv1);
    }
}

// ---------------- depthwise 3x3, 4 pixels per block (3x reuse) ----------------
__global__ void __launch_bounds__(256) dwconv_q4(
    const __half2* __restrict__ y, const float* __restrict__ w2,
    const float* __restrict__ b2, const float* __restrict__ s2,
    const float* __restrict__ h2b, __half2* __restrict__ out)
{
    int grp = blockIdx.x;            // 0..4095
    int b = grp >> 8;                // 256 4-pixel groups per image
    int p4 = (grp & 255) * 4;
    int sy = p4 >> 5, sx0 = p4 & 31;
    const __half2* yb = y + (size_t)(b << 10) * 768;
    for (int c2 = threadIdx.x; c2 < 768; c2 += 256){
        int c = 2*c2;
        float w[9][2];
        #pragma unroll
        for (int t=0;t<9;t++){ w[t][0]=w2[c*9+t]; w[t][1]=w2[(c+1)*9+t]; }
        float bb0=b2[c], bb1=b2[c+1], ss0=s2[c], ss1=s2[c+1], hh0=h2b[c], hh1=h2b[c+1];
        float ax[4]={0.f,0.f,0.f,0.f}, ay[4]={0.f,0.f,0.f,0.f};
        float2 cen[4];
        #pragma unroll
        for (int dy=0; dy<3; dy++){
            int iy = sy + dy - 1;
            if ((unsigned)iy >= 32u) continue;
            #pragma unroll
            for (int dxx=0; dxx<6; dxx++){
                int ix = sx0 + dxx - 1;
                if ((unsigned)ix >= 32u) continue;
                float2 fv = __half22float2(yb[(size_t)((iy<<5)+ix)*768 + c2]);
                if (dy==1 && dxx>=1 && dxx<=4) cen[dxx-1] = fv;
                #pragma unroll
                for (int i=0;i<4;i++){
                    int dr = dxx - i;          // kernel column index
                    if (dr >= 0 && dr < 3){
                        ax[i] += fv.x * w[dy*3+dr][0];
                        ay[i] += fv.y * w[dy*3+dr][1];
                    }
                }
            }
        }
        #pragma unroll
        for (int i=0;i<4;i++){
            float vx = (ax[i] + bb0)*ss0 + hh0;
            float vy = (ay[i] + bb1)*ss1 + hh1;
            out[(size_t)((b<<10) + p4 + i)*768 + c2] =
                __floats2half2_rn(cen[i].x + gelu_f(vx), cen[i].y + gelu_f(vy));
        }
    }
}

// ---------------- SE gate ----------------
__global__ void se_kernel(const float* __restrict__ part, const float* __restrict__ cw,
                          const float* __restrict__ cb, const float* __restrict__ ew,
                          const float* __restrict__ eb, float* __restrict__ wout)
{
    __shared__ float m[CC];
    __shared__ float cv[96];
    int b = blockIdx.x, t = threadIdx.x;    // 384 threads
    m[t] = part[b*CC + t] * (1.0f/1024.0f);
    __syncthreads();
    if (t < 96){
        float a = cb[t];
        for (int k=0;k<CC;k++) a += m[k]*cw[t*CC + k];
        cv[t] = gelu_f(a);
    }
    __syncthreads();
    float a = eb[t];
    for (int k=0;k<96;k++) a += cv[k]*ew[t*96 + k];
    wout[b*CC + t] = a;
}

// ---------------- cls rows: out[b,0,:] = x1 + h2*w ----------------
__global__ void final_cls_kernel(const float* __restrict__ x1, const __half* __restrict__ h2,
                                 const float* __restrict__ w, float* __restrict__ out)
{
    int b = blockIdx.x, t = threadIdx.x;    // 384 threads
    size_t i = (size_t)b*NN*CC + t;
    out[i] = x1[i] + __half2float(h2[i]) * w[b*CC + t];
}

// ---------------- launcher ----------------
extern "C" void kernel_launch(void* const* d_in, const int* in_sizes, int n_in,
                              void* d_out, int out_size)
{
    const float* x       = (const float*)d_in[0];
    const float* ln1_g   = (const float*)d_in[1];
    const float* ln1_b   = (const float*)d_in[2];
    const float* qkv_w   = (const float*)d_in[3];
    const float* proj_w  = (const float*)d_in[4];
    const float* proj_b  = (const float*)d_in[5];
    const float* ln2_g   = (const float*)d_in[6];
    const float* ln2_b   = (const float*)d_in[7];
    const float* conv1_w = (const float*)d_in[8];
    const float* conv1_b = (const float*)d_in[9];
    const float* conv2_w = (const float*)d_in[10];
    const float* conv2_b = (const float*)d_in[11];
    const float* conv3_w = (const float*)d_in[12];
    const float* conv3_b = (const float*)d_in[13];
    const float* bn1_s   = (const float*)d_in[14];
    const float* bn1_b   = (const float*)d_in[15];
    const float* bn2_s   = (const float*)d_in[16];
    const float* bn2_b   = (const float*)d_in[17];
    const float* bn3_s   = (const float*)d_in[18];
    const float* bn3_b   = (const float*)d_in[19];
    const float* comp_w  = (const float*)d_in[20];
    const float* comp_b  = (const float*)d_in[21];
    const float* exc_w   = (const float*)d_in[22];
    const float* exc_b   = (const float*)d_in[23];
    float* out = (float*)d_out;

    static bool init = false;
    static __half *p_hh, *p_qkvh, *p_oh, *p_h2h, *p_yh, *p_y2h, *p_wq, *p_wp, *p_w1, *p_w3;
    static float *p_x1, *p_part2, *p_w;
    if (!init){
        cudaGetSymbolAddress((void**)&p_hh,    g_hh);
        cudaGetSymbolAddress((void**)&p_qkvh,  g_qkvh);
        cudaGetSymbolAddress((void**)&p_oh,    g_oh);
        cudaGetSymbolAddress((void**)&p_x1,    g_x1);
        cudaGetSymbolAddress((void**)&p_h2h,   g_h2h);
        cudaGetSymbolAddress((void**)&p_yh,    g_yh);
        cudaGetSymbolAddress((void**)&p_y2h,   g_y2h);
        cudaGetSymbolAddress((void**)&p_part2, g_part2);
        cudaGetSymbolAddress((void**)&p_w,     g_w);
        cudaGetSymbolAddress((void**)&p_wq,    g_wq);
        cudaGetSymbolAddress((void**)&p_wp,    g_wp);
        cudaGetSymbolAddress((void**)&p_w1,    g_w1);
        cudaGetSymbolAddress((void**)&p_w3,    g_w3);
        cudaFuncSetAttribute(gemm_h<5,false,128>, cudaFuncAttributeMaxDynamicSharedMemorySize, GEMM_SMEM_MT(128));
        cudaFuncSetAttribute(gemm_h<1,false,64>,  cudaFuncAttributeMaxDynamicSharedMemorySize, GEMM_SMEM_MT(64));
        cudaFuncSetAttribute(gemm_h<2,true,128>,  cudaFuncAttributeMaxDynamicSharedMemorySize, GEMM_SMEM_MT(128));
        cudaFuncSetAttribute(gemm_h<4,false,64>,  cudaFuncAttributeMaxDynamicSharedMemorySize, GEMM_SMEM_MT(64));
        cudaFuncSetAttribute(attn_h, cudaFuncAttributeMaxDynamicSharedMemorySize, ATTN_SMEM);
        init = true;
    }

    // 0. weight conversions + psum zero (single launch)
    f2h_all<<<512, 256>>>(qkv_w, p_wq, proj_w, p_wp, conv1_w, p_w1, conv3_w, p_w3, p_part2);
    // 1. LN1 -> fp16 h
    ln_kernel<<<MTOT, 128>>>(x, ln1_g, ln1_b, p_hh);
    // 2. QKV = h @ qkv_w^T -> fp16, q columns pre-scaled by 0.125
    gemm_h<5,false,128><<<dim3(9,129), 256, GEMM_SMEM_MT(128)>>>(p_hh, p_wq, p_qkvh,
        MTOT, 3*CC, CC, nullptr, nullptr, nullptr, nullptr, nullptr);
    // 3. attention -> fp16 o
    attn_h<<<BB*HH*9, 256, ATTN_SMEM>>>(p_qkvh, p_oh);
    // 4. x1 = x + o @ proj_w^T + proj_b (fp32), 64-row tiles for wave balance
    gemm_h<1,false,64><<<dim3(3,257), 256, GEMM_SMEM_MT(64)>>>(p_oh, p_wp, p_x1,
        MTOT, CC, CC, proj_b, nullptr, nullptr, x, nullptr);
    // 5. LN2 -> fp16 h2
    ln_kernel<<<MTOT, 128>>>(p_x1, ln2_g, ln2_b, p_h2h);
    // 6. conv1 + BN1 + GELU -> fp16 y (tokens only)
    gemm_h<2,true,128><<<dim3(12,128), 256, GEMM_SMEM_MT(128)>>>(p_h2h, p_w1, p_yh,
        MTOK, HID, CC, conv1_b, bn1_s, bn1_b, nullptr, nullptr);
    // 7. depthwise 3x3 + BN2 -> fp16 y2 (4 pixels/block)
    dwconv_q4<<<4096, 256>>>((const __half2*)p_yh, conv2_w, conv2_b, bn2_s, bn2_b,
                             (__half2*)p_y2h);
    // 8. conv3 + BN3 fused tail, 64-row tiles
    gemm_h<4,false,64><<<dim3(3,256), 256, GEMM_SMEM_MT(64)>>>(p_y2h, p_w3, out,
        MTOK, CC, HID, conv3_b, bn3_s, bn3_b, p_x1, p_part2);
    // 9. SE gate
    se_kernel<<<BB, CC>>>(p_part2, comp_w, comp_b, exc_w, exc_b, p_w);
    // 10. cls rows
    final_cls_kernel<<<BB, CC>>>(p_x1, p_h2h, p_w, out);
}